// round 8
// baseline (speedup 1.0000x reference)
#include <cuda_runtime.h>
#include <cstdint>

#define NN   50000
#define NE   800000
#define NG   50
#define DIN  256
#define DMID 128
#define DOUT 256
#define DE   128
#define DP   64

#define S1CAP  24576
#define E2CAPC 24576
#define E3CAP  4096
#define S2CAP  4096
#define DEGCAP 64
#define E1SLOTS (S1CAP * DEGCAP)

// ---------- zeroed-per-launch buffer (floats) ----------
#define OFF_AGGX1  0u            // [NN][128] zeroed per-S2-row
#define OFF_AGGE1  6400000u      // [NN][64]  zeroed per-S2-row
#define OFF_CNT    9600000u      // 16 ints: 1:nE2 2:nE3 3:nS1 4:nS2
#define OFF_S1F    9600016u
#define OFF_S2F    9650016u
#define OFF_FILL   9700016u
#define ZTOTAL     9750016u

__device__ __align__(16) float d_zbuf[ZTOTAL];

// ---------- persistent scratch ----------
#define SOFF_X1    0u                     // [NN][128] node-indexed
#define SOFF_X2    6400000u               // [NN][128] node-indexed
#define SOFF_E1C   12800000u              // [E2CAPC][64]
#define SOFF_E2C   14372864u              // [E3CAP][64]
#define SOFF_CATA  14635008u              // [S1CAP][400]
#define SOFF_W1    24465408u              // [656][128]
#define SOFF_WE1   24549376u              // [640][64]
#define SOFF_W2    24590336u              // [320][128]
#define SOFF_WE2   24631296u              // [320][64]
#define SOFF_CFE   24651776u              // [64]
#define STOTAL     24651840u

__device__ __align__(16) float d_sbuf[STOTAL];

#define IOFF_CSRSRC 0u                    // [E1SLOTS]
#define IOFF_CSREID 1572864u              // [E1SLOTS]
#define IOFF_START  3145728u              // [NN]
#define IOFF_E2LIST 3195728u              // [E2CAPC]
#define IOFF_SRCE2  3220304u
#define IOFF_DSTE2  3244880u
#define IOFF_SLOTE2 3269456u              // [NE]
#define IOFF_E3LIST 4069456u
#define IOFF_SRCE3  4073552u
#define IOFF_DSTE3  4077648u
#define IOFF_GE3    4081744u
#define IOFF_E1SLOT 4085840u
#define IOFF_S1LIST 4089936u              // [NN]
#define IOFF_S2LIST 4139936u              // [NN]
#define IOFF_MAST   4189936u
#define ITOTAL      4190000u

__device__ __align__(16) int d_ibuf[ITOTAL];

__device__ __forceinline__ void redv4(float* p, float a, float b, float c, float d) {
    asm volatile("red.global.add.v4.f32 [%0], {%1,%2,%3,%4};"
                 :: "l"(p), "f"(a), "f"(b), "f"(c), "f"(d) : "memory");
}

__device__ __forceinline__ unsigned f2tf32(float f) {
    unsigned u;
    asm("cvt.rna.tf32.f32 %0, %1;" : "=r"(u) : "f"(f));
    return u;
}

// warp-wide multi-item allocation: thread contributes cntt items, returns its base offset
__device__ __forceinline__ int multi_alloc(int cntt, int* counter) {
    const unsigned mask = 0xffffffffu;
    int lane = threadIdx.x & 31;
    int incl = cntt;
    #pragma unroll
    for (int d = 1; d < 32; d <<= 1) {
        int v = __shfl_up_sync(mask, incl, d);
        if (lane >= d) incl += v;
    }
    int total = __shfl_sync(mask, incl, 31);
    int base = 0;
    if (lane == 31 && total) base = atomicAdd(counter, total);
    base = __shfl_sync(mask, base, 31);
    return base + incl - cntt;
}

// ---------------- fused init ----------------
__global__ __launch_bounds__(256) void init_k(
    const int* __restrict__ batch,
    const float* __restrict__ wproj, const float* __restrict__ bproj,
    const float* __restrict__ ws1, const float* __restrict__ wmx1,
    const float* __restrict__ wme1,
    const float* __restrict__ wes1, const float* __restrict__ wed1,
    const float* __restrict__ wee1, const float* __restrict__ be1,
    const float* __restrict__ ws2, const float* __restrict__ wmx2,
    const float* __restrict__ wme2,
    const float* __restrict__ wes2, const float* __restrict__ wed2,
    const float* __restrict__ wee2)
{
    int b = blockIdx.x, tid = threadIdx.x;
    if (b < 196) {
        int n = b * 256 + tid;
        if (n < NN) {
            int* s1f = (int*)(d_zbuf + OFF_S1F);
            int* s2f = (int*)(d_zbuf + OFF_S2F);
            int* fil = (int*)(d_zbuf + OFF_FILL);
            int g = batch[n];
            bool m = (n == 0) || (batch[n - 1] != g);
            s1f[n] = m ? 1 : 0;
            s2f[n] = m ? 1 : 0;     // bit0 = is-master
            fil[n] = 0;
            if (m) d_ibuf[IOFF_MAST + g] = n;
        }
        if (b == 0 && tid < 16) ((int*)(d_zbuf + OFF_CNT))[tid] = 0;
    } else {
        int r = (b - 196) * 2 + (tid >> 7);
        int j = tid & 127;
        if (r < 656) {                                   // W1 [656][128]
            float v = 0.f;
            if (r < 256) v = ws1[r * 128 + j];
            else if (r < 512) v = wmx1[(r - 256) * 128 + j];
            else if (r < 640) {
                for (int k = 0; k < DP; k++) v = fmaf(wproj[(r - 512) * DP + k], wme1[k * 128 + j], v);
            } else if (r == 640) {
                for (int k = 0; k < DP; k++) v = fmaf(bproj[k], wme1[k * 128 + j], v);
            }
            d_sbuf[SOFF_W1 + r * 128 + j] = v;
        } else if (r < 1296) {                           // WE1 [640][64]
            int rr = r - 656;
            if (j < 64) {
                float v;
                if (rr < 256) v = wes1[rr * 64 + j];
                else if (rr < 512) v = wed1[(rr - 256) * 64 + j];
                else {
                    v = 0.f;
                    for (int k = 0; k < DP; k++) v = fmaf(wproj[(rr - 512) * DP + k], wee1[k * 64 + j], v);
                }
                d_sbuf[SOFF_WE1 + rr * 64 + j] = v;
                if (rr == 0) {
                    float c = 0.f;
                    for (int k = 0; k < DP; k++) c = fmaf(bproj[k], wee1[k * 64 + j], c);
                    d_sbuf[SOFF_CFE + j] = c + be1[j];
                }
            }
        } else if (r < 1616) {                           // W2 [320][128]
            int rr = r - 1296;
            float v;
            if (rr < 128) v = ws2[rr * 128 + j];
            else if (rr < 256) v = wmx2[(rr - 128) * 128 + j];
            else v = wme2[(rr - 256) * 128 + j];
            d_sbuf[SOFF_W2 + rr * 128 + j] = v;
        } else if (r < 1936) {                           // WE2 [320][64]
            int rr = r - 1616;
            if (j < 64) {
                float v;
                if (rr < 128) v = wes2[rr * 64 + j];
                else if (rr < 256) v = wed2[(rr - 128) * 64 + j];
                else v = wee2[(rr - 256) * 64 + j];
                d_sbuf[SOFF_WE2 + rr * 64 + j] = v;
            }
        }
    }
}

// ---------------- vectorized set construction ----------------
__global__ void pass_e3(const int* __restrict__ src, const int* __restrict__ dst,
                        const int* __restrict__ batch) {
    int* cnt = (int*)(d_zbuf + OFF_CNT);
    int* s2f = (int*)(d_zbuf + OFF_S2F);
    int* s1f = (int*)(d_zbuf + OFF_S1F);
    const int4* dst4 = (const int4*)dst;
    const int N4 = NE / 4;
    int base = blockIdx.x * blockDim.x + threadIdx.x;
    int stride = gridDim.x * blockDim.x;
    for (int idx = base; ; idx += stride) {
        int dd[4] = {0, 0, 0, 0};
        int f[4] = {0, 0, 0, 0};
        if (idx < N4) {
            int4 d4 = dst4[idx];
            dd[0] = d4.x; dd[1] = d4.y; dd[2] = d4.z; dd[3] = d4.w;
            f[0] = s2f[dd[0]] & 1; f[1] = s2f[dd[1]] & 1;
            f[2] = s2f[dd[2]] & 1; f[3] = s2f[dd[3]] & 1;
        }
        int cntt = f[0] + f[1] + f[2] + f[3];
        int ofs = multi_alloc(cntt, cnt + 2);
        #pragma unroll
        for (int k = 0; k < 4; k++) {
            if (f[k]) {
                int j = ofs++;
                if (j < E3CAP) {
                    int e = idx * 4 + k;
                    int ss = src[e];
                    d_ibuf[IOFF_E3LIST + j] = e;
                    d_ibuf[IOFF_SRCE3 + j] = ss;
                    d_ibuf[IOFF_DSTE3 + j] = dd[k];
                    d_ibuf[IOFF_GE3 + j] = batch[dd[k]];
                    atomicOr(&s2f[ss], 2);
                    s1f[ss] = 1;
                }
            }
        }
        if (__all_sync(0xffffffffu, idx >= N4)) break;
    }
}

__global__ void pass_e2(const int* __restrict__ src, const int* __restrict__ dst) {
    int* cnt = (int*)(d_zbuf + OFF_CNT);
    int* s2f = (int*)(d_zbuf + OFF_S2F);
    int* s1f = (int*)(d_zbuf + OFF_S1F);
    const int4* dst4 = (const int4*)dst;
    const int4* src4 = (const int4*)src;
    const int N4 = NE / 4;
    int base = blockIdx.x * blockDim.x + threadIdx.x;
    int stride = gridDim.x * blockDim.x;
    for (int idx = base; ; idx += stride) {
        int dd[4] = {0, 0, 0, 0}, ss[4] = {0, 0, 0, 0};
        int f[4] = {0, 0, 0, 0};
        if (idx < N4) {
            int4 d4 = dst4[idx];
            dd[0] = d4.x; dd[1] = d4.y; dd[2] = d4.z; dd[3] = d4.w;
            f[0] = s2f[dd[0]] != 0; f[1] = s2f[dd[1]] != 0;
            f[2] = s2f[dd[2]] != 0; f[3] = s2f[dd[3]] != 0;
            if (f[0] | f[1] | f[2] | f[3]) {
                int4 s4 = src4[idx];
                ss[0] = s4.x; ss[1] = s4.y; ss[2] = s4.z; ss[3] = s4.w;
            }
        }
        int cntt = f[0] + f[1] + f[2] + f[3];
        int ofs = multi_alloc(cntt, cnt + 1);
        #pragma unroll
        for (int k = 0; k < 4; k++) {
            if (f[k]) {
                int j = ofs++;
                if (j < E2CAPC) {
                    int e = idx * 4 + k;
                    d_ibuf[IOFF_E2LIST + j] = e;
                    d_ibuf[IOFF_SRCE2 + j] = ss[k];
                    d_ibuf[IOFF_DSTE2 + j] = dd[k];
                    d_ibuf[IOFF_SLOTE2 + e] = j;
                    s1f[ss[k]] = 1;
                }
            }
        }
        if (__all_sync(0xffffffffu, idx >= N4)) break;
    }
}

__global__ void compact_nodes() {
    int* cnt = (int*)(d_zbuf + OFF_CNT);
    const int4* s2f4 = (const int4*)(d_zbuf + OFF_S2F);
    const int4* s1f4 = (const int4*)(d_zbuf + OFF_S1F);
    const int N4 = NN / 4;  // 12500
    int base = blockIdx.x * blockDim.x + threadIdx.x;
    int stride = gridDim.x * blockDim.x;
    for (int idx = base; ; idx += stride) {
        int f2[4] = {0, 0, 0, 0}, f1[4] = {0, 0, 0, 0};
        if (idx < N4) {
            int4 v2 = s2f4[idx];
            int4 v1 = s1f4[idx];
            f2[0] = v2.x != 0; f2[1] = v2.y != 0; f2[2] = v2.z != 0; f2[3] = v2.w != 0;
            f1[0] = v1.x != 0; f1[1] = v1.y != 0; f1[2] = v1.z != 0; f1[3] = v1.w != 0;
        }
        int c2 = f2[0] + f2[1] + f2[2] + f2[3];
        int o2 = multi_alloc(c2, cnt + 4);
        #pragma unroll
        for (int k = 0; k < 4; k++)
            if (f2[k]) d_ibuf[IOFF_S2LIST + (o2++)] = idx * 4 + k;
        int c1 = f1[0] + f1[1] + f1[2] + f1[3];
        int o1 = multi_alloc(c1, cnt + 3);
        #pragma unroll
        for (int k = 0; k < 4; k++)
            if (f1[k]) {
                int n = idx * 4 + k;
                d_ibuf[IOFF_S1LIST + o1] = n;
                d_ibuf[IOFF_START + n] = o1 * DEGCAP;
                o1++;
            }
        if (__all_sync(0xffffffffu, idx >= N4)) break;
    }
}

// fill CSR buckets + (folded) e1slot build + per-S2-row agg zeroing
__global__ void fill_e1(const int* __restrict__ src, const int* __restrict__ dst) {
    int* cnt = (int*)(d_zbuf + OFF_CNT);
    int* s1f = (int*)(d_zbuf + OFF_S1F);
    int* fil = (int*)(d_zbuf + OFF_FILL);
    const int4* dst4 = (const int4*)dst;
    const int4* src4 = (const int4*)src;
    const int N4 = NE / 4;
    int tid0 = blockIdx.x * blockDim.x + threadIdx.x;
    int stride = gridDim.x * blockDim.x;
    for (int idx = tid0; idx < N4; idx += stride) {
        int4 d4 = dst4[idx];
        int dd[4] = {d4.x, d4.y, d4.z, d4.w};
        int f[4];
        f[0] = s1f[dd[0]] != 0; f[1] = s1f[dd[1]] != 0;
        f[2] = s1f[dd[2]] != 0; f[3] = s1f[dd[3]] != 0;
        if (f[0] | f[1] | f[2] | f[3]) {
            int4 s4 = src4[idx];
            int ss[4] = {s4.x, s4.y, s4.z, s4.w};
            #pragma unroll
            for (int k = 0; k < 4; k++) {
                if (f[k]) {
                    int p = atomicAdd(&fil[dd[k]], 1);
                    if (p < DEGCAP) {
                        int pos = d_ibuf[IOFF_START + dd[k]] + p;
                        if (pos < E1SLOTS) {
                            d_ibuf[IOFF_CSRSRC + pos] = ss[k];
                            d_ibuf[IOFF_CSREID + pos] = idx * 4 + k;
                        }
                    }
                }
            }
        }
    }
    // folded prep: e1slot + zero S2 agg rows (inputs all ready before this launch)
    int nE3 = min(cnt[2], E3CAP);
    for (int i = tid0; i < nE3; i += stride)
        d_ibuf[IOFF_E1SLOT + i] = d_ibuf[IOFF_SLOTE2 + d_ibuf[IOFF_E3LIST + i]];
    int nS2 = min(cnt[4], S2CAP);
    float4 z = make_float4(0.f, 0.f, 0.f, 0.f);
    int total2 = nS2 * 48;
    for (int t = tid0; t < total2; t += stride) {
        int i = t / 48, q = t - i * 48;
        int n = d_ibuf[IOFF_S2LIST + i];
        if (q < 32) reinterpret_cast<float4*>(d_zbuf + OFF_AGGX1 + (size_t)n * 128)[q] = z;
        else        reinterpret_cast<float4*>(d_zbuf + OFF_AGGE1 + (size_t)n * 64)[q - 32] = z;
    }
}

// warp handles (node i, chunk c): c=0 -> x[0:128), c=1 -> x[128:256), c=2 -> eattr[0:128)
__global__ __launch_bounds__(256) void gather_l1(const float* __restrict__ x,
                                                 const float* __restrict__ eattr) {
    int* cnt = (int*)(d_zbuf + OFF_CNT);
    int nS1 = min(cnt[3], S1CAP);
    const int* fil = (const int*)(d_zbuf + OFF_FILL);
    float* catA = d_sbuf + SOFF_CATA;
    int lane = threadIdx.x & 31;
    int w = (blockIdx.x * blockDim.x + threadIdx.x) >> 5;
    int W = (gridDim.x * blockDim.x) >> 5;
    int total = nS1 * 3;
    for (int t = w; t < total; t += W) {
        int i = t / 3, c = t - i * 3;
        int n = d_ibuf[IOFF_S1LIST + i];
        int deg = min(fil[n], DEGCAP);
        int st = i * DEGCAP, end = st + deg;
        float a0 = 0.f, a1 = 0.f, a2 = 0.f, a3 = 0.f;
        for (int base = st; base < end; base += 32) {
            int cn = end - base; if (cn > 32) cn = 32;
            int midx = 0;
            if (base + lane < end)
                midx = (c == 2) ? d_ibuf[IOFF_CSREID + base + lane]
                                : d_ibuf[IOFF_CSRSRC + base + lane];
            for (int j = 0; j < cn; j++) {
                int r = __shfl_sync(0xffffffffu, midx, j);
                const float* p = (c == 2)
                    ? (eattr + (size_t)r * DE + lane * 4)
                    : (x + (size_t)r * DIN + c * 128 + lane * 4);
                float4 v = *reinterpret_cast<const float4*>(p);
                a0 += v.x; a1 += v.y; a2 += v.z; a3 += v.w;
            }
        }
        float* row = catA + (size_t)i * 400;
        *reinterpret_cast<float4*>(row + c * 128 + lane * 4) = make_float4(a0, a1, a2, a3);
        if (c == 0 && lane < 4) {
            float4 tail = make_float4(0.f, 0.f, 0.f, 0.f);
            if (lane == 0) tail.x = (float)deg;
            *reinterpret_cast<float4*>(row + 384 + lane * 4) = tail;
        }
    }
}

// ---------------- segmented-A TF32 GEMM (BN=64), dual-problem launch ----------------
struct GArgs {
    const float* A0; const int* i0; int K0;
    const float* A1; const int* i1; int K1;
    const float* A2; const int* i2; int K2;
    const float* B; const float* bias;
    float* C; const int* idxC;
    const int* Mptr; int Mcap; int N; int relu;
};

__device__ __forceinline__ void gemm_body(
    const GArgs g, int bid, int nblocks,
    unsigned (*As)[132], unsigned (*Bs)[68], int (*rIdx)[128])
{
    int M = *g.Mptr; if (M > g.Mcap) M = g.Mcap;
    const int K = g.K0 + g.K1 + g.K2;
    const int BM = 128, BK = 16, BN_ = 64;
    const int tid = threadIdx.x;
    const int lane = tid & 31, warp = tid >> 5;
    const int wm = warp >> 1, wn = warp & 1;
    const int gid = lane >> 2, tg = lane & 3;
    const int mTiles = (M + BM - 1) / BM;
    const int nTiles = g.N / BN_;
    const int tiles = mTiles * nTiles;

    for (int t = bid; t < tiles; t += nblocks) {
        const int mt = t / nTiles, nt = t % nTiles;
        const int m0 = mt * BM, n0 = nt * BN_;

        for (int s = tid; s < 3 * BM; s += 256) {
            int seg = s >> 7, row = s & 127;
            int m = m0 + row;
            int Ks = seg == 0 ? g.K0 : (seg == 1 ? g.K1 : g.K2);
            int r = 0;
            if (Ks > 0 && m < M) {
                const int* ix = seg == 0 ? g.i0 : (seg == 1 ? g.i1 : g.i2);
                r = ix ? ix[m] : m;
            }
            rIdx[seg][row] = r;
        }
        __syncthreads();

        float c[2][4][4];
        #pragma unroll
        for (int mf = 0; mf < 2; mf++)
            #pragma unroll
            for (int nf = 0; nf < 4; nf++)
                #pragma unroll
                for (int q = 0; q < 4; q++) c[mf][nf][q] = 0.f;

        for (int k0 = 0; k0 < K; k0 += BK) {
            const float* Ap; int segi, w, kl;
            if (k0 < g.K0)             { Ap = g.A0; segi = 0; w = g.K0; kl = k0; }
            else if (k0 < g.K0 + g.K1) { Ap = g.A1; segi = 1; w = g.K1; kl = k0 - g.K0; }
            else                       { Ap = g.A2; segi = 2; w = g.K2; kl = k0 - g.K0 - g.K1; }
            #pragma unroll
            for (int l = 0; l < 2; l++) {
                int s = tid + l * 256;
                int row = s >> 2, q = s & 3;
                int m = m0 + row;
                float4 v = make_float4(0.f, 0.f, 0.f, 0.f);
                if (m < M) {
                    int r = rIdx[segi][row];
                    v = *reinterpret_cast<const float4*>(Ap + (size_t)r * w + kl + q * 4);
                }
                As[q * 4 + 0][row] = f2tf32(v.x);
                As[q * 4 + 1][row] = f2tf32(v.y);
                As[q * 4 + 2][row] = f2tf32(v.z);
                As[q * 4 + 3][row] = f2tf32(v.w);
            }
            {
                int kk = tid >> 4, nq = tid & 15;
                float4 v = *reinterpret_cast<const float4*>(g.B + (size_t)(k0 + kk) * g.N + n0 + nq * 4);
                Bs[kk][nq * 4 + 0] = f2tf32(v.x);
                Bs[kk][nq * 4 + 1] = f2tf32(v.y);
                Bs[kk][nq * 4 + 2] = f2tf32(v.z);
                Bs[kk][nq * 4 + 3] = f2tf32(v.w);
            }
            __syncthreads();
            #pragma unroll
            for (int kk = 0; kk < BK; kk += 8) {
                unsigned a[2][4], b[4][2];
                #pragma unroll
                for (int mf = 0; mf < 2; mf++) {
                    int am = wm * 32 + mf * 16;
                    a[mf][0] = As[kk + tg][am + gid];
                    a[mf][1] = As[kk + tg][am + gid + 8];
                    a[mf][2] = As[kk + tg + 4][am + gid];
                    a[mf][3] = As[kk + tg + 4][am + gid + 8];
                }
                #pragma unroll
                for (int nf = 0; nf < 4; nf++) {
                    int bn = wn * 32 + nf * 8;
                    b[nf][0] = Bs[kk + tg][bn + gid];
                    b[nf][1] = Bs[kk + tg + 4][bn + gid];
                }
                #pragma unroll
                for (int mf = 0; mf < 2; mf++)
                    #pragma unroll
                    for (int nf = 0; nf < 4; nf++)
                        asm volatile(
                            "mma.sync.aligned.m16n8k8.row.col.f32.tf32.tf32.f32 "
                            "{%0,%1,%2,%3},{%4,%5,%6,%7},{%8,%9},{%0,%1,%2,%3};"
                            : "+f"(c[mf][nf][0]), "+f"(c[mf][nf][1]),
                              "+f"(c[mf][nf][2]), "+f"(c[mf][nf][3])
                            : "r"(a[mf][0]), "r"(a[mf][1]), "r"(a[mf][2]), "r"(a[mf][3]),
                              "r"(b[nf][0]), "r"(b[nf][1]));
            }
            __syncthreads();
        }
        #pragma unroll
        for (int mf = 0; mf < 2; mf++) {
            #pragma unroll
            for (int half = 0; half < 2; half++) {
                int mrow = m0 + wm * 32 + mf * 16 + gid + half * 8;
                if (mrow >= M) continue;
                int r = g.idxC ? g.idxC[mrow] : mrow;
                #pragma unroll
                for (int nf = 0; nf < 4; nf++) {
                    int col = n0 + wn * 32 + nf * 8 + tg * 2;
                    float* cp = g.C + (size_t)r * g.N + col;
                    float v0 = c[mf][nf][half * 2 + 0];
                    float v1 = c[mf][nf][half * 2 + 1];
                    if (g.bias) { v0 += g.bias[col]; v1 += g.bias[col + 1]; }
                    if (g.relu) { v0 = fmaxf(v0, 0.f); v1 = fmaxf(v1, 0.f); }
                    *reinterpret_cast<float2*>(cp) = make_float2(v0, v1);
                }
            }
        }
        __syncthreads();
    }
}

__global__ __launch_bounds__(256) void gemm_dual(GArgs a, GArgs b, int split) {
    __shared__ unsigned As[16][132];
    __shared__ unsigned Bs[16][68];
    __shared__ int rIdx[3][128];
    if ((int)blockIdx.x < split) gemm_body(a, blockIdx.x, split, As, Bs, rIdx);
    else gemm_body(b, blockIdx.x - split, gridDim.x - split, As, Bs, rIdx);
}

__global__ void scatter_l2() {
    int* cnt = (int*)(d_zbuf + OFF_CNT);
    int nE2 = min(cnt[1], E2CAPC);
    float* aggX1 = d_zbuf + OFF_AGGX1;
    float* aggE1 = d_zbuf + OFF_AGGE1;
    const float* x1  = d_sbuf + SOFF_X1;
    const float* e1c = d_sbuf + SOFF_E1C;
    int lane = threadIdx.x & 31;
    int w = (blockIdx.x * blockDim.x + threadIdx.x) >> 5;
    int W = (gridDim.x * blockDim.x) >> 5;
    for (int i = w; i < nE2; i += W) {
        int s = d_ibuf[IOFF_SRCE2 + i], d = d_ibuf[IOFF_DSTE2 + i];
        float4 hv = *reinterpret_cast<const float4*>(x1 + (size_t)s * DMID + lane * 4);
        redv4(aggX1 + (size_t)d * DMID + lane * 4, hv.x, hv.y, hv.z, hv.w);
        if (lane < 16) {
            float4 ev = *reinterpret_cast<const float4*>(e1c + (size_t)i * DP + lane * 4);
            redv4(aggE1 + (size_t)d * DP + lane * 4, ev.x, ev.y, ev.z, ev.w);
        }
    }
}

// fused per-graph E3 gather + output GEMM: one block per graph
__global__ __launch_bounds__(256) void final_k(
    const float* __restrict__ ws3, const float* __restrict__ bs3,
    const float* __restrict__ wmx3, const float* __restrict__ wme3,
    float* __restrict__ out)
{
    __shared__ int elist[128];
    __shared__ int ecnt;
    __shared__ float aggx[128];
    __shared__ float agge[64];
    int* cnt = (int*)(d_zbuf + OFF_CNT);
    int nE3 = min(cnt[2], E3CAP);
    int g = blockIdx.x, tid = threadIdx.x;
    if (tid == 0) ecnt = 0;
    __syncthreads();
    for (int e = tid; e < nE3; e += 256) {
        if (d_ibuf[IOFF_GE3 + e] == g) {
            int p = atomicAdd(&ecnt, 1);
            if (p < 128) elist[p] = e;
        }
    }
    __syncthreads();
    int ne = min(ecnt, 128);
    const float* x2 = d_sbuf + SOFF_X2;
    const float* e2c = d_sbuf + SOFF_E2C;
    if (tid < 128) {
        float a = 0.f;
        for (int i = 0; i < ne; i++) {
            int e = elist[i];
            a += x2[(size_t)d_ibuf[IOFF_SRCE3 + e] * DMID + tid];
        }
        aggx[tid] = a;
    } else if (tid < 192) {
        float a = 0.f;
        for (int i = 0; i < ne; i++)
            a += e2c[(size_t)elist[i] * DP + (tid - 128)];
        agge[tid - 128] = a;
    }
    __syncthreads();
    int m = d_ibuf[IOFF_MAST + g];
    float s = bs3[tid];
    const float* xr = x2 + (size_t)m * DMID;
    #pragma unroll 4
    for (int k = 0; k < DMID; k++) s = fmaf(xr[k], ws3[k * DOUT + tid], s);
    #pragma unroll 4
    for (int k = 0; k < DMID; k++) s = fmaf(aggx[k], wmx3[k * DOUT + tid], s);
    #pragma unroll 4
    for (int k = 0; k < DP; k++) s = fmaf(agge[k], wme3[k * DOUT + tid], s);
    out[(size_t)g * DOUT + tid] = s;
}

extern "C" void kernel_launch(void* const* d_in, const int* in_sizes, int n_in,
                              void* d_out, int out_size) {
    const float* x         = (const float*)d_in[0];
    const int*   eidx      = (const int*)d_in[1];
    const float* edge_attr = (const float*)d_in[2];
    const int*   batch     = (const int*)d_in[3];
    const float* wproj     = (const float*)d_in[4];
    const float* bproj     = (const float*)d_in[5];
    const float* ws1  = (const float*)d_in[6],  *bs1 = (const float*)d_in[7];
    const float* wmx1 = (const float*)d_in[8],  *wme1 = (const float*)d_in[9];
    const float* wes1 = (const float*)d_in[10], *wed1 = (const float*)d_in[11];
    const float* wee1 = (const float*)d_in[12];
    const float* be1  = (const float*)d_in[13];
    const float* ws2  = (const float*)d_in[14], *bs2 = (const float*)d_in[15];
    const float* wmx2 = (const float*)d_in[16], *wme2 = (const float*)d_in[17];
    const float* wes2 = (const float*)d_in[18], *wed2 = (const float*)d_in[19];
    const float* wee2 = (const float*)d_in[20], *be2 = (const float*)d_in[21];
    const float* ws3  = (const float*)d_in[22], *bs3 = (const float*)d_in[23];
    const float* wmx3 = (const float*)d_in[24], *wme3 = (const float*)d_in[25];
    (void)n_in; (void)in_sizes;

    const int* src = eidx;
    const int* dst = eidx + NE;

    void* pz; cudaGetSymbolAddress(&pz, d_zbuf);
    void* ps; cudaGetSymbolAddress(&ps, d_sbuf);
    void* pi; cudaGetSymbolAddress(&pi, d_ibuf);
    float* zb = (float*)pz;
    float* sb = (float*)ps;
    int*   ib = (int*)pi;

    float* aggX1 = zb + OFF_AGGX1;
    float* aggE1 = zb + OFF_AGGE1;
    int*   cnt   = (int*)(zb + OFF_CNT);
    float* x1   = sb + SOFF_X1;
    float* x2   = sb + SOFF_X2;
    float* e1c  = sb + SOFF_E1C;
    float* e2c  = sb + SOFF_E2C;
    float* catA = sb + SOFF_CATA;
    float* W1   = sb + SOFF_W1;
    float* WE1  = sb + SOFF_WE1;
    float* W2   = sb + SOFF_W2;
    float* WE2  = sb + SOFF_WE2;
    float* cfe  = sb + SOFF_CFE;
    int* S1list = ib + IOFF_S1LIST;
    int* S2list = ib + IOFF_S2LIST;
    int* srcE2  = ib + IOFF_SRCE2;
    int* dstE2  = ib + IOFF_DSTE2;
    int* E2list = ib + IOFF_E2LIST;
    int* srcE3  = ib + IOFF_SRCE3;
    int* dstE3  = ib + IOFF_DSTE3;
    int* e1slot = ib + IOFF_E1SLOT;

    init_k<<<1164, 256>>>(batch, wproj, bproj, ws1, wmx1, wme1, wes1, wed1, wee1, be1,
                          ws2, wmx2, wme2, wes2, wed2, wee2);
    pass_e3<<<400, 256>>>(src, dst, batch);
    pass_e2<<<400, 256>>>(src, dst);
    compact_nodes<<<64, 256>>>();
    fill_e1<<<800, 256>>>(src, dst);
    gather_l1<<<1024, 256>>>(x, edge_attr);

    // dual GEMM 1: x1 (S1 rows, N=128)  ||  e1c (E2 rows, N=64)
    GArgs gx1 = { x, S1list, DIN, catA, nullptr, 400, nullptr, nullptr, 0,
                  W1, bs1, x1, S1list, cnt + 3, S1CAP, DMID, 1 };
    GArgs ge1 = { x, srcE2, DIN, x, dstE2, DIN, edge_attr, E2list, DE,
                  WE1, cfe, e1c, nullptr, cnt + 1, E2CAPC, DP, 1 };
    gemm_dual<<<296, 256>>>(gx1, ge1, 198);

    scatter_l2<<<512, 256>>>();

    // dual GEMM 2: x2 (S2 rows, N=128)  ||  e2c (E3 rows, N=64)
    GArgs gx2 = { x1, S2list, DMID, aggX1, S2list, DMID, aggE1, S2list, DP,
                  W2, bs2, x2, S2list, cnt + 4, S2CAP, DMID, 1 };
    GArgs ge2 = { x1, srcE3, DMID, x1, dstE3, DMID, e1c, e1slot, DP,
                  WE2, be2, e2c, nullptr, cnt + 2, E3CAP, DP, 1 };
    gemm_dual<<<24, 256>>>(gx2, ge2, 16);

    final_k<<<NG, 256>>>(ws3, bs3, wmx3, wme3, (float*)d_out);
    (void)out_size;
}

// round 9
// speedup vs baseline: 1.3266x; 1.3266x over previous
#include <cuda_runtime.h>
#include <cstdint>

#define NN   50000
#define NE   800000
#define NG   50
#define DIN  256
#define DMID 128
#define DOUT 256
#define DE   128
#define DP   64

#define S1CAP  24576
#define E2CAPC 24576
#define E3CAP  4096
#define S2CAP  4096
#define DEGCAP 64
#define E1SLOTS (S1CAP * DEGCAP)

// ---------- zeroed-per-launch buffer (floats) ----------
#define OFF_AGGX1  0u            // [NN][128] zeroed per-S2-row
#define OFF_AGGE1  6400000u      // [NN][64]  zeroed per-S2-row
#define OFF_CNT    9600000u      // 16 ints: 1:nE2 2:nE3 3:nS1 4:nS2
#define OFF_S1F    9600016u
#define OFF_S2F    9650016u
#define OFF_FILL   9700016u
#define ZTOTAL     9750016u

__device__ __align__(16) float d_zbuf[ZTOTAL];

// ---------- persistent scratch ----------
#define SOFF_X1    0u                     // [NN][128] node-indexed
#define SOFF_X2    6400000u               // [NN][128] node-indexed
#define SOFF_E1C   12800000u              // [E2CAPC][64]
#define SOFF_E2C   14372864u              // [E3CAP][64]
#define SOFF_CATA  14635008u              // [S1CAP][400]
#define SOFF_W1    24465408u              // [656][128]
#define SOFF_WE1   24549376u              // [640][64]
#define SOFF_W2    24590336u              // [320][128]
#define SOFF_WE2   24631296u              // [320][64]
#define SOFF_CFE   24651776u              // [64]
#define STOTAL     24651840u

__device__ __align__(16) float d_sbuf[STOTAL];

#define IOFF_CSRSRC 0u                    // [E1SLOTS]
#define IOFF_CSREID 1572864u              // [E1SLOTS]
#define IOFF_START  3145728u              // [NN]
#define IOFF_E2LIST 3195728u              // [E2CAPC]
#define IOFF_SRCE2  3220304u
#define IOFF_DSTE2  3244880u
#define IOFF_SLOTE2 3269456u              // [NE]
#define IOFF_E3LIST 4069456u
#define IOFF_SRCE3  4073552u
#define IOFF_DSTE3  4077648u
#define IOFF_GE3    4081744u
#define IOFF_E1SLOT 4085840u
#define IOFF_S1LIST 4089936u              // [NN]
#define IOFF_S2LIST 4139936u              // [NN]
#define IOFF_MAST   4189936u
#define ITOTAL      4190000u

__device__ __align__(16) int d_ibuf[ITOTAL];

__device__ __forceinline__ void redv4(float* p, float a, float b, float c, float d) {
    asm volatile("red.global.add.v4.f32 [%0], {%1,%2,%3,%4};"
                 :: "l"(p), "f"(a), "f"(b), "f"(c), "f"(d) : "memory");
}

__device__ __forceinline__ unsigned f2tf32(float f) {
    unsigned u;
    asm("cvt.rna.tf32.f32 %0, %1;" : "=r"(u) : "f"(f));
    return u;
}

// warp-wide multi-item allocation
__device__ __forceinline__ int multi_alloc(int cntt, int* counter) {
    const unsigned mask = 0xffffffffu;
    int lane = threadIdx.x & 31;
    int incl = cntt;
    #pragma unroll
    for (int d = 1; d < 32; d <<= 1) {
        int v = __shfl_up_sync(mask, incl, d);
        if (lane >= d) incl += v;
    }
    int total = __shfl_sync(mask, incl, 31);
    int base = 0;
    if (lane == 31 && total) base = atomicAdd(counter, total);
    base = __shfl_sync(mask, base, 31);
    return base + incl - cntt;
}

// ---------------- init: flags + masters + counters (critical path) ----------------
__global__ __launch_bounds__(256) void init_flags(const int* __restrict__ batch) {
    int n = blockIdx.x * 256 + threadIdx.x;
    if (n < NN) {
        int* s1f = (int*)(d_zbuf + OFF_S1F);
        int* s2f = (int*)(d_zbuf + OFF_S2F);
        int* fil = (int*)(d_zbuf + OFF_FILL);
        int g = batch[n];
        bool m = (n == 0) || (batch[n - 1] != g);
        s1f[n] = m ? 1 : 0;
        s2f[n] = m ? 1 : 0;     // bit0 = is-master
        fil[n] = 0;
        if (m) d_ibuf[IOFF_MAST + g] = n;
    }
    if (blockIdx.x == 0 && threadIdx.x < 16) ((int*)(d_zbuf + OFF_CNT))[threadIdx.x] = 0;
}

// ---------------- init: stacked weights (side stream) ----------------
__global__ __launch_bounds__(256) void init_weights(
    const float* __restrict__ wproj, const float* __restrict__ bproj,
    const float* __restrict__ ws1, const float* __restrict__ wmx1,
    const float* __restrict__ wme1,
    const float* __restrict__ wes1, const float* __restrict__ wed1,
    const float* __restrict__ wee1, const float* __restrict__ be1,
    const float* __restrict__ ws2, const float* __restrict__ wmx2,
    const float* __restrict__ wme2,
    const float* __restrict__ wes2, const float* __restrict__ wed2,
    const float* __restrict__ wee2)
{
    int r = blockIdx.x * 2 + (threadIdx.x >> 7);
    int j = threadIdx.x & 127;
    if (r < 656) {                                   // W1 [656][128]
        float v = 0.f;
        if (r < 256) v = ws1[r * 128 + j];
        else if (r < 512) v = wmx1[(r - 256) * 128 + j];
        else if (r < 640) {
            for (int k = 0; k < DP; k++) v = fmaf(wproj[(r - 512) * DP + k], wme1[k * 128 + j], v);
        } else if (r == 640) {
            for (int k = 0; k < DP; k++) v = fmaf(bproj[k], wme1[k * 128 + j], v);
        }
        d_sbuf[SOFF_W1 + r * 128 + j] = v;
    } else if (r < 1296) {                           // WE1 [640][64]
        int rr = r - 656;
        if (j < 64) {
            float v;
            if (rr < 256) v = wes1[rr * 64 + j];
            else if (rr < 512) v = wed1[(rr - 256) * 64 + j];
            else {
                v = 0.f;
                for (int k = 0; k < DP; k++) v = fmaf(wproj[(rr - 512) * DP + k], wee1[k * 64 + j], v);
            }
            d_sbuf[SOFF_WE1 + rr * 64 + j] = v;
            if (rr == 0) {
                float c = 0.f;
                for (int k = 0; k < DP; k++) c = fmaf(bproj[k], wee1[k * 64 + j], c);
                d_sbuf[SOFF_CFE + j] = c + be1[j];
            }
        }
    } else if (r < 1616) {                           // W2 [320][128]
        int rr = r - 1296;
        float v;
        if (rr < 128) v = ws2[rr * 128 + j];
        else if (rr < 256) v = wmx2[(rr - 128) * 128 + j];
        else v = wme2[(rr - 256) * 128 + j];
        d_sbuf[SOFF_W2 + rr * 128 + j] = v;
    } else if (r < 1936) {                           // WE2 [320][64]
        int rr = r - 1616;
        if (j < 64) {
            float v;
            if (rr < 128) v = wes2[rr * 64 + j];
            else if (rr < 256) v = wed2[(rr - 128) * 64 + j];
            else v = wee2[(rr - 256) * 64 + j];
            d_sbuf[SOFF_WE2 + rr * 64 + j] = v;
        }
    }
}

// ---------------- vectorized set construction ----------------
__global__ void pass_e3(const int* __restrict__ src, const int* __restrict__ dst,
                        const int* __restrict__ batch) {
    int* cnt = (int*)(d_zbuf + OFF_CNT);
    int* s2f = (int*)(d_zbuf + OFF_S2F);
    int* s1f = (int*)(d_zbuf + OFF_S1F);
    const int4* dst4 = (const int4*)dst;
    const int N4 = NE / 4;
    int base = blockIdx.x * blockDim.x + threadIdx.x;
    int stride = gridDim.x * blockDim.x;
    for (int idx = base; ; idx += stride) {
        int dd[4] = {0, 0, 0, 0};
        int f[4] = {0, 0, 0, 0};
        if (idx < N4) {
            int4 d4 = dst4[idx];
            dd[0] = d4.x; dd[1] = d4.y; dd[2] = d4.z; dd[3] = d4.w;
            f[0] = s2f[dd[0]] & 1; f[1] = s2f[dd[1]] & 1;
            f[2] = s2f[dd[2]] & 1; f[3] = s2f[dd[3]] & 1;
        }
        int cntt = f[0] + f[1] + f[2] + f[3];
        int ofs = multi_alloc(cntt, cnt + 2);
        #pragma unroll
        for (int k = 0; k < 4; k++) {
            if (f[k]) {
                int j = ofs++;
                if (j < E3CAP) {
                    int e = idx * 4 + k;
                    int ss = src[e];
                    d_ibuf[IOFF_E3LIST + j] = e;
                    d_ibuf[IOFF_SRCE3 + j] = ss;
                    d_ibuf[IOFF_DSTE3 + j] = dd[k];
                    d_ibuf[IOFF_GE3 + j] = batch[dd[k]];
                    atomicOr(&s2f[ss], 2);
                    s1f[ss] = 1;
                }
            }
        }
        if (__all_sync(0xffffffffu, idx >= N4)) break;
    }
}

__global__ void pass_e2(const int* __restrict__ src, const int* __restrict__ dst) {
    int* cnt = (int*)(d_zbuf + OFF_CNT);
    int* s2f = (int*)(d_zbuf + OFF_S2F);
    int* s1f = (int*)(d_zbuf + OFF_S1F);
    const int4* dst4 = (const int4*)dst;
    const int4* src4 = (const int4*)src;
    const int N4 = NE / 4;
    int base = blockIdx.x * blockDim.x + threadIdx.x;
    int stride = gridDim.x * blockDim.x;
    for (int idx = base; ; idx += stride) {
        int dd[4] = {0, 0, 0, 0}, ss[4] = {0, 0, 0, 0};
        int f[4] = {0, 0, 0, 0};
        if (idx < N4) {
            int4 d4 = dst4[idx];
            dd[0] = d4.x; dd[1] = d4.y; dd[2] = d4.z; dd[3] = d4.w;
            f[0] = s2f[dd[0]] != 0; f[1] = s2f[dd[1]] != 0;
            f[2] = s2f[dd[2]] != 0; f[3] = s2f[dd[3]] != 0;
            if (f[0] | f[1] | f[2] | f[3]) {
                int4 s4 = src4[idx];
                ss[0] = s4.x; ss[1] = s4.y; ss[2] = s4.z; ss[3] = s4.w;
            }
        }
        int cntt = f[0] + f[1] + f[2] + f[3];
        int ofs = multi_alloc(cntt, cnt + 1);
        #pragma unroll
        for (int k = 0; k < 4; k++) {
            if (f[k]) {
                int j = ofs++;
                if (j < E2CAPC) {
                    int e = idx * 4 + k;
                    d_ibuf[IOFF_E2LIST + j] = e;
                    d_ibuf[IOFF_SRCE2 + j] = ss[k];
                    d_ibuf[IOFF_DSTE2 + j] = dd[k];
                    d_ibuf[IOFF_SLOTE2 + e] = j;
                    s1f[ss[k]] = 1;
                }
            }
        }
        if (__all_sync(0xffffffffu, idx >= N4)) break;
    }
}

__global__ void compact_nodes() {
    int* cnt = (int*)(d_zbuf + OFF_CNT);
    const int4* s2f4 = (const int4*)(d_zbuf + OFF_S2F);
    const int4* s1f4 = (const int4*)(d_zbuf + OFF_S1F);
    const int N4 = NN / 4;  // 12500
    int base = blockIdx.x * blockDim.x + threadIdx.x;
    int stride = gridDim.x * blockDim.x;
    for (int idx = base; ; idx += stride) {
        int f2[4] = {0, 0, 0, 0}, f1[4] = {0, 0, 0, 0};
        if (idx < N4) {
            int4 v2 = s2f4[idx];
            int4 v1 = s1f4[idx];
            f2[0] = v2.x != 0; f2[1] = v2.y != 0; f2[2] = v2.z != 0; f2[3] = v2.w != 0;
            f1[0] = v1.x != 0; f1[1] = v1.y != 0; f1[2] = v1.z != 0; f1[3] = v1.w != 0;
        }
        int c2 = f2[0] + f2[1] + f2[2] + f2[3];
        int o2 = multi_alloc(c2, cnt + 4);
        #pragma unroll
        for (int k = 0; k < 4; k++)
            if (f2[k]) d_ibuf[IOFF_S2LIST + (o2++)] = idx * 4 + k;
        int c1 = f1[0] + f1[1] + f1[2] + f1[3];
        int o1 = multi_alloc(c1, cnt + 3);
        #pragma unroll
        for (int k = 0; k < 4; k++)
            if (f1[k]) {
                int n = idx * 4 + k;
                d_ibuf[IOFF_S1LIST + o1] = n;
                d_ibuf[IOFF_START + n] = o1 * DEGCAP;
                o1++;
            }
        if (__all_sync(0xffffffffu, idx >= N4)) break;
    }
}

// fill CSR buckets + (folded) e1slot build + per-S2-row agg zeroing
__global__ void fill_e1(const int* __restrict__ src, const int* __restrict__ dst) {
    int* cnt = (int*)(d_zbuf + OFF_CNT);
    int* s1f = (int*)(d_zbuf + OFF_S1F);
    int* fil = (int*)(d_zbuf + OFF_FILL);
    const int4* dst4 = (const int4*)dst;
    const int4* src4 = (const int4*)src;
    const int N4 = NE / 4;
    int tid0 = blockIdx.x * blockDim.x + threadIdx.x;
    int stride = gridDim.x * blockDim.x;
    for (int idx = tid0; idx < N4; idx += stride) {
        int4 d4 = dst4[idx];
        int dd[4] = {d4.x, d4.y, d4.z, d4.w};
        int f[4];
        f[0] = s1f[dd[0]] != 0; f[1] = s1f[dd[1]] != 0;
        f[2] = s1f[dd[2]] != 0; f[3] = s1f[dd[3]] != 0;
        if (f[0] | f[1] | f[2] | f[3]) {
            int4 s4 = src4[idx];
            int ss[4] = {s4.x, s4.y, s4.z, s4.w};
            #pragma unroll
            for (int k = 0; k < 4; k++) {
                if (f[k]) {
                    int p = atomicAdd(&fil[dd[k]], 1);
                    if (p < DEGCAP) {
                        int pos = d_ibuf[IOFF_START + dd[k]] + p;
                        if (pos < E1SLOTS) {
                            d_ibuf[IOFF_CSRSRC + pos] = ss[k];
                            d_ibuf[IOFF_CSREID + pos] = idx * 4 + k;
                        }
                    }
                }
            }
        }
    }
    int nE3 = min(cnt[2], E3CAP);
    for (int i = tid0; i < nE3; i += stride)
        d_ibuf[IOFF_E1SLOT + i] = d_ibuf[IOFF_SLOTE2 + d_ibuf[IOFF_E3LIST + i]];
    int nS2 = min(cnt[4], S2CAP);
    float4 z = make_float4(0.f, 0.f, 0.f, 0.f);
    int total2 = nS2 * 48;
    for (int t = tid0; t < total2; t += stride) {
        int i = t / 48, q = t - i * 48;
        int n = d_ibuf[IOFF_S2LIST + i];
        if (q < 32) reinterpret_cast<float4*>(d_zbuf + OFF_AGGX1 + (size_t)n * 128)[q] = z;
        else        reinterpret_cast<float4*>(d_zbuf + OFF_AGGE1 + (size_t)n * 64)[q - 32] = z;
    }
}

// warp handles (node i, chunk c): c=0 -> x[0:128), c=1 -> x[128:256), c=2 -> eattr[0:128)
__global__ __launch_bounds__(256) void gather_l1(const float* __restrict__ x,
                                                 const float* __restrict__ eattr) {
    int* cnt = (int*)(d_zbuf + OFF_CNT);
    int nS1 = min(cnt[3], S1CAP);
    const int* fil = (const int*)(d_zbuf + OFF_FILL);
    float* catA = d_sbuf + SOFF_CATA;
    int lane = threadIdx.x & 31;
    int w = (blockIdx.x * blockDim.x + threadIdx.x) >> 5;
    int W = (gridDim.x * blockDim.x) >> 5;
    int total = nS1 * 3;
    for (int t = w; t < total; t += W) {
        int i = t / 3, c = t - i * 3;
        int n = d_ibuf[IOFF_S1LIST + i];
        int deg = min(fil[n], DEGCAP);
        int st = i * DEGCAP, end = st + deg;
        float a0 = 0.f, a1 = 0.f, a2 = 0.f, a3 = 0.f;
        for (int base = st; base < end; base += 32) {
            int cn = end - base; if (cn > 32) cn = 32;
            int midx = 0;
            if (base + lane < end)
                midx = (c == 2) ? d_ibuf[IOFF_CSREID + base + lane]
                                : d_ibuf[IOFF_CSRSRC + base + lane];
            int j = 0;
            for (; j + 1 < cn; j += 2) {
                int r0 = __shfl_sync(0xffffffffu, midx, j);
                int r1 = __shfl_sync(0xffffffffu, midx, j + 1);
                const float* p0 = (c == 2)
                    ? (eattr + (size_t)r0 * DE + lane * 4)
                    : (x + (size_t)r0 * DIN + c * 128 + lane * 4);
                const float* p1 = (c == 2)
                    ? (eattr + (size_t)r1 * DE + lane * 4)
                    : (x + (size_t)r1 * DIN + c * 128 + lane * 4);
                float4 v0 = *reinterpret_cast<const float4*>(p0);
                float4 v1 = *reinterpret_cast<const float4*>(p1);
                a0 += v0.x + v1.x; a1 += v0.y + v1.y;
                a2 += v0.z + v1.z; a3 += v0.w + v1.w;
            }
            if (j < cn) {
                int r0 = __shfl_sync(0xffffffffu, midx, j);
                const float* p0 = (c == 2)
                    ? (eattr + (size_t)r0 * DE + lane * 4)
                    : (x + (size_t)r0 * DIN + c * 128 + lane * 4);
                float4 v0 = *reinterpret_cast<const float4*>(p0);
                a0 += v0.x; a1 += v0.y; a2 += v0.z; a3 += v0.w;
            }
        }
        float* row = catA + (size_t)i * 400;
        *reinterpret_cast<float4*>(row + c * 128 + lane * 4) = make_float4(a0, a1, a2, a3);
        if (c == 0 && lane < 4) {
            float4 tail = make_float4(0.f, 0.f, 0.f, 0.f);
            if (lane == 0) tail.x = (float)deg;
            *reinterpret_cast<float4*>(row + 384 + lane * 4) = tail;
        }
    }
}

// ---------------- segmented-A TF32 GEMM (BN=64) with register prefetch ----------------
struct GArgs {
    const float* A0; const int* i0; int K0;
    const float* A1; const int* i1; int K1;
    const float* A2; const int* i2; int K2;
    const float* B; const float* bias;
    float* C; const int* idxC;
    const int* Mptr; int Mcap; int N; int relu;
};

__device__ __forceinline__ void gemm_body(
    const GArgs g, int bid, int nblocks,
    unsigned (*As)[132], unsigned (*Bs)[68], int (*rIdx)[128])
{
    int M = *g.Mptr; if (M > g.Mcap) M = g.Mcap;
    const int K = g.K0 + g.K1 + g.K2;
    const int nk = K / 16;
    const int BM = 128, BK = 16, BN_ = 64;
    const int tid = threadIdx.x;
    const int lane = tid & 31, warp = tid >> 5;
    const int wm = warp >> 1, wn = warp & 1;
    const int gid = lane >> 2, tg = lane & 3;
    const int mTiles = (M + BM - 1) / BM;
    const int nTiles = g.N / BN_;
    const int tiles = mTiles * nTiles;

    const int arow = tid >> 2, aq = tid & 3;       // A: this thread loads rows arow, arow+64
    const int bkk = tid >> 4, bnq = tid & 15;      // B: one float4 per thread

    for (int t = bid; t < tiles; t += nblocks) {
        const int mt = t / nTiles, nt = t % nTiles;
        const int m0 = mt * BM, n0 = nt * BN_;

        for (int s = tid; s < 3 * BM; s += 256) {
            int seg = s >> 7, row = s & 127;
            int m = m0 + row;
            int Ks = seg == 0 ? g.K0 : (seg == 1 ? g.K1 : g.K2);
            int r = 0;
            if (Ks > 0 && m < M) {
                const int* ix = seg == 0 ? g.i0 : (seg == 1 ? g.i1 : g.i2);
                r = ix ? ix[m] : m;
            }
            rIdx[seg][row] = r;
        }
        __syncthreads();

        float c[2][4][4];
        #pragma unroll
        for (int mf = 0; mf < 2; mf++)
            #pragma unroll
            for (int nf = 0; nf < 4; nf++)
                #pragma unroll
                for (int q = 0; q < 4; q++) c[mf][nf][q] = 0.f;

        float4 va0, va1, vb;
        // prefetch k-iter 0
        {
            const float* Ap; int segi, w, kl;
            int k0 = 0;
            if (k0 < g.K0)             { Ap = g.A0; segi = 0; w = g.K0; kl = k0; }
            else if (k0 < g.K0 + g.K1) { Ap = g.A1; segi = 1; w = g.K1; kl = k0 - g.K0; }
            else                       { Ap = g.A2; segi = 2; w = g.K2; kl = k0 - g.K0 - g.K1; }
            va0 = make_float4(0.f, 0.f, 0.f, 0.f);
            va1 = va0;
            if (m0 + arow < M)
                va0 = *reinterpret_cast<const float4*>(Ap + (size_t)rIdx[segi][arow] * w + kl + aq * 4);
            if (m0 + arow + 64 < M)
                va1 = *reinterpret_cast<const float4*>(Ap + (size_t)rIdx[segi][arow + 64] * w + kl + aq * 4);
            vb = *reinterpret_cast<const float4*>(g.B + (size_t)(k0 + bkk) * g.N + n0 + bnq * 4);
        }

        for (int ki = 0; ki < nk; ki++) {
            // store prefetched regs to smem
            As[aq * 4 + 0][arow] = f2tf32(va0.x);
            As[aq * 4 + 1][arow] = f2tf32(va0.y);
            As[aq * 4 + 2][arow] = f2tf32(va0.z);
            As[aq * 4 + 3][arow] = f2tf32(va0.w);
            As[aq * 4 + 0][arow + 64] = f2tf32(va1.x);
            As[aq * 4 + 1][arow + 64] = f2tf32(va1.y);
            As[aq * 4 + 2][arow + 64] = f2tf32(va1.z);
            As[aq * 4 + 3][arow + 64] = f2tf32(va1.w);
            Bs[bkk][bnq * 4 + 0] = f2tf32(vb.x);
            Bs[bkk][bnq * 4 + 1] = f2tf32(vb.y);
            Bs[bkk][bnq * 4 + 2] = f2tf32(vb.z);
            Bs[bkk][bnq * 4 + 3] = f2tf32(vb.w);
            __syncthreads();

            // prefetch next k-iter (overlaps with mma below)
            if (ki + 1 < nk) {
                int k0 = (ki + 1) * BK;
                const float* Ap; int segi, w, kl;
                if (k0 < g.K0)             { Ap = g.A0; segi = 0; w = g.K0; kl = k0; }
                else if (k0 < g.K0 + g.K1) { Ap = g.A1; segi = 1; w = g.K1; kl = k0 - g.K0; }
                else                       { Ap = g.A2; segi = 2; w = g.K2; kl = k0 - g.K0 - g.K1; }
                va0 = make_float4(0.f, 0.f, 0.f, 0.f);
                va1 = va0;
                if (m0 + arow < M)
                    va0 = *reinterpret_cast<const float4*>(Ap + (size_t)rIdx[segi][arow] * w + kl + aq * 4);
                if (m0 + arow + 64 < M)
                    va1 = *reinterpret_cast<const float4*>(Ap + (size_t)rIdx[segi][arow + 64] * w + kl + aq * 4);
                vb = *reinterpret_cast<const float4*>(g.B + (size_t)(k0 + bkk) * g.N + n0 + bnq * 4);
            }

            #pragma unroll
            for (int kk = 0; kk < BK; kk += 8) {
                unsigned a[2][4], b[4][2];
                #pragma unroll
                for (int mf = 0; mf < 2; mf++) {
                    int am = wm * 32 + mf * 16;
                    a[mf][0] = As[kk + tg][am + gid];
                    a[mf][1] = As[kk + tg][am + gid + 8];
                    a[mf][2] = As[kk + tg + 4][am + gid];
                    a[mf][3] = As[kk + tg + 4][am + gid + 8];
                }
                #pragma unroll
                for (int nf = 0; nf < 4; nf++) {
                    int bn = wn * 32 + nf * 8;
                    b[nf][0] = Bs[kk + tg][bn + gid];
                    b[nf][1] = Bs[kk + tg + 4][bn + gid];
                }
                #pragma unroll
                for (int mf = 0; mf < 2; mf++)
                    #pragma unroll
                    for (int nf = 0; nf < 4; nf++)
                        asm volatile(
                            "mma.sync.aligned.m16n8k8.row.col.f32.tf32.tf32.f32 "
                            "{%0,%1,%2,%3},{%4,%5,%6,%7},{%8,%9},{%0,%1,%2,%3};"
                            : "+f"(c[mf][nf][0]), "+f"(c[mf][nf][1]),
                              "+f"(c[mf][nf][2]), "+f"(c[mf][nf][3])
                            : "r"(a[mf][0]), "r"(a[mf][1]), "r"(a[mf][2]), "r"(a[mf][3]),
                              "r"(b[nf][0]), "r"(b[nf][1]));
            }
            __syncthreads();
        }
        #pragma unroll
        for (int mf = 0; mf < 2; mf++) {
            #pragma unroll
            for (int half = 0; half < 2; half++) {
                int mrow = m0 + wm * 32 + mf * 16 + gid + half * 8;
                if (mrow >= M) continue;
                int r = g.idxC ? g.idxC[mrow] : mrow;
                #pragma unroll
                for (int nf = 0; nf < 4; nf++) {
                    int col = n0 + wn * 32 + nf * 8 + tg * 2;
                    float* cp = g.C + (size_t)r * g.N + col;
                    float v0 = c[mf][nf][half * 2 + 0];
                    float v1 = c[mf][nf][half * 2 + 1];
                    if (g.bias) { v0 += g.bias[col]; v1 += g.bias[col + 1]; }
                    if (g.relu) { v0 = fmaxf(v0, 0.f); v1 = fmaxf(v1, 0.f); }
                    *reinterpret_cast<float2*>(cp) = make_float2(v0, v1);
                }
            }
        }
        __syncthreads();
    }
}

__global__ __launch_bounds__(256) void gemm_one(GArgs a) {
    __shared__ unsigned As[16][132];
    __shared__ unsigned Bs[16][68];
    __shared__ int rIdx[3][128];
    gemm_body(a, blockIdx.x, gridDim.x, As, Bs, rIdx);
}

__global__ __launch_bounds__(256) void gemm_dual(GArgs a, GArgs b, int split) {
    __shared__ unsigned As[16][132];
    __shared__ unsigned Bs[16][68];
    __shared__ int rIdx[3][128];
    if ((int)blockIdx.x < split) gemm_body(a, blockIdx.x, split, As, Bs, rIdx);
    else gemm_body(b, blockIdx.x - split, gridDim.x - split, As, Bs, rIdx);
}

__global__ void scatter_l2() {
    int* cnt = (int*)(d_zbuf + OFF_CNT);
    int nE2 = min(cnt[1], E2CAPC);
    float* aggX1 = d_zbuf + OFF_AGGX1;
    float* aggE1 = d_zbuf + OFF_AGGE1;
    const float* x1  = d_sbuf + SOFF_X1;
    const float* e1c = d_sbuf + SOFF_E1C;
    int lane = threadIdx.x & 31;
    int w = (blockIdx.x * blockDim.x + threadIdx.x) >> 5;
    int W = (gridDim.x * blockDim.x) >> 5;
    for (int i = w; i < nE2; i += W) {
        int s = d_ibuf[IOFF_SRCE2 + i], d = d_ibuf[IOFF_DSTE2 + i];
        float4 hv = *reinterpret_cast<const float4*>(x1 + (size_t)s * DMID + lane * 4);
        redv4(aggX1 + (size_t)d * DMID + lane * 4, hv.x, hv.y, hv.z, hv.w);
        if (lane < 16) {
            float4 ev = *reinterpret_cast<const float4*>(e1c + (size_t)i * DP + lane * 4);
            redv4(aggE1 + (size_t)d * DP + lane * 4, ev.x, ev.y, ev.z, ev.w);
        }
    }
}

// fused per-graph E3 gather + output GEMM: one block per graph
__global__ __launch_bounds__(256) void final_k(
    const float* __restrict__ ws3, const float* __restrict__ bs3,
    const float* __restrict__ wmx3, const float* __restrict__ wme3,
    float* __restrict__ out)
{
    __shared__ int elist[128];
    __shared__ int ecnt;
    __shared__ float aggx[128];
    __shared__ float agge[64];
    int* cnt = (int*)(d_zbuf + OFF_CNT);
    int nE3 = min(cnt[2], E3CAP);
    int g = blockIdx.x, tid = threadIdx.x;
    if (tid == 0) ecnt = 0;
    __syncthreads();
    for (int e = tid; e < nE3; e += 256) {
        if (d_ibuf[IOFF_GE3 + e] == g) {
            int p = atomicAdd(&ecnt, 1);
            if (p < 128) elist[p] = e;
        }
    }
    __syncthreads();
    int ne = min(ecnt, 128);
    const float* x2 = d_sbuf + SOFF_X2;
    const float* e2c = d_sbuf + SOFF_E2C;
    if (tid < 128) {
        float a = 0.f;
        for (int i = 0; i < ne; i++) {
            int e = elist[i];
            a += x2[(size_t)d_ibuf[IOFF_SRCE3 + e] * DMID + tid];
        }
        aggx[tid] = a;
    } else if (tid < 192) {
        float a = 0.f;
        for (int i = 0; i < ne; i++)
            a += e2c[(size_t)elist[i] * DP + (tid - 128)];
        agge[tid - 128] = a;
    }
    __syncthreads();
    int m = d_ibuf[IOFF_MAST + g];
    float s = bs3[tid];
    const float* xr = x2 + (size_t)m * DMID;
    #pragma unroll 4
    for (int k = 0; k < DMID; k++) s = fmaf(xr[k], ws3[k * DOUT + tid], s);
    #pragma unroll 4
    for (int k = 0; k < DMID; k++) s = fmaf(aggx[k], wmx3[k * DOUT + tid], s);
    #pragma unroll 4
    for (int k = 0; k < DP; k++) s = fmaf(agge[k], wme3[k * DOUT + tid], s);
    out[(size_t)g * DOUT + tid] = s;
}

extern "C" void kernel_launch(void* const* d_in, const int* in_sizes, int n_in,
                              void* d_out, int out_size) {
    const float* x         = (const float*)d_in[0];
    const int*   eidx      = (const int*)d_in[1];
    const float* edge_attr = (const float*)d_in[2];
    const int*   batch     = (const int*)d_in[3];
    const float* wproj     = (const float*)d_in[4];
    const float* bproj     = (const float*)d_in[5];
    const float* ws1  = (const float*)d_in[6],  *bs1 = (const float*)d_in[7];
    const float* wmx1 = (const float*)d_in[8],  *wme1 = (const float*)d_in[9];
    const float* wes1 = (const float*)d_in[10], *wed1 = (const float*)d_in[11];
    const float* wee1 = (const float*)d_in[12];
    const float* be1  = (const float*)d_in[13];
    const float* ws2  = (const float*)d_in[14], *bs2 = (const float*)d_in[15];
    const float* wmx2 = (const float*)d_in[16], *wme2 = (const float*)d_in[17];
    const float* wes2 = (const float*)d_in[18], *wed2 = (const float*)d_in[19];
    const float* wee2 = (const float*)d_in[20], *be2 = (const float*)d_in[21];
    const float* ws3  = (const float*)d_in[22], *bs3 = (const float*)d_in[23];
    const float* wmx3 = (const float*)d_in[24], *wme3 = (const float*)d_in[25];
    (void)n_in; (void)in_sizes;

    const int* src = eidx;
    const int* dst = eidx + NE;

    void* pz; cudaGetSymbolAddress(&pz, d_zbuf);
    void* ps; cudaGetSymbolAddress(&ps, d_sbuf);
    void* pi; cudaGetSymbolAddress(&pi, d_ibuf);
    float* zb = (float*)pz;
    float* sb = (float*)ps;
    int*   ib = (int*)pi;

    float* aggX1 = zb + OFF_AGGX1;
    float* aggE1 = zb + OFF_AGGE1;
    int*   cnt   = (int*)(zb + OFF_CNT);
    float* x1   = sb + SOFF_X1;
    float* x2   = sb + SOFF_X2;
    float* e1c  = sb + SOFF_E1C;
    float* e2c  = sb + SOFF_E2C;
    float* catA = sb + SOFF_CATA;
    float* W1   = sb + SOFF_W1;
    float* WE1  = sb + SOFF_WE1;
    float* W2   = sb + SOFF_W2;
    float* WE2  = sb + SOFF_WE2;
    float* cfe  = sb + SOFF_CFE;
    int* S1list = ib + IOFF_S1LIST;
    int* S2list = ib + IOFF_S2LIST;
    int* srcE2  = ib + IOFF_SRCE2;
    int* dstE2  = ib + IOFF_DSTE2;
    int* E2list = ib + IOFF_E2LIST;
    int* srcE3  = ib + IOFF_SRCE3;
    int* dstE3  = ib + IOFF_DSTE3;
    int* e1slot = ib + IOFF_E1SLOT;

    // side stream + events (created once on the uncaptured correctness call;
    // during capture the record/wait pairs become pure graph edges)
    static cudaStream_t sB = nullptr;
    static cudaEvent_t evStart = nullptr, evE2 = nullptr, evE1C = nullptr;
    if (!sB) {
        cudaStreamCreateWithFlags(&sB, cudaStreamNonBlocking);
        cudaEventCreateWithFlags(&evStart, cudaEventDisableTiming);
        cudaEventCreateWithFlags(&evE2, cudaEventDisableTiming);
        cudaEventCreateWithFlags(&evE1C, cudaEventDisableTiming);
    }

    // fork: side stream builds stacked weights while main does set construction
    cudaEventRecord(evStart, 0);
    cudaStreamWaitEvent(sB, evStart, 0);
    init_weights<<<968, 256, 0, sB>>>(wproj, bproj, ws1, wmx1, wme1, wes1, wed1, wee1, be1,
                                      ws2, wmx2, wme2, wes2, wed2, wee2);

    // main chain
    init_flags<<<196, 256>>>(batch);
    pass_e3<<<400, 256>>>(src, dst, batch);
    pass_e2<<<400, 256>>>(src, dst);
    cudaEventRecord(evE2, 0);
    compact_nodes<<<64, 256>>>();
    fill_e1<<<800, 256>>>(src, dst);
    gather_l1<<<1024, 256>>>(x, edge_attr);

    // side stream: e1c GEMM (needs pass_e2 outputs + weights) overlaps with
    // compact/fill/gather/x1-GEMM on main
    cudaStreamWaitEvent(sB, evE2, 0);
    GArgs ge1 = { x, srcE2, DIN, x, dstE2, DIN, edge_attr, E2list, DE,
                  WE1, cfe, e1c, nullptr, cnt + 1, E2CAPC, DP, 1 };
    gemm_one<<<120, 256, 0, sB>>>(ge1);
    cudaEventRecord(evE1C, sB);

    // main: x1 GEMM
    GArgs gx1 = { x, S1list, DIN, catA, nullptr, 400, nullptr, nullptr, 0,
                  W1, bs1, x1, S1list, cnt + 3, S1CAP, DMID, 1 };
    gemm_one<<<240, 256>>>(gx1);

    // join: scatter_l2 needs both x1 and e1c
    cudaStreamWaitEvent(0, evE1C, 0);
    scatter_l2<<<512, 256>>>();

    // dual GEMM 2: x2 (S2 rows, N=128)  ||  e2c (E3 rows, N=64)
    GArgs gx2 = { x1, S2list, DMID, aggX1, S2list, DMID, aggE1, S2list, DP,
                  W2, bs2, x2, S2list, cnt + 4, S2CAP, DMID, 1 };
    GArgs ge2 = { x1, srcE3, DMID, x1, dstE3, DMID, e1c, e1slot, DP,
                  WE2, be2, e2c, nullptr, cnt + 2, E3CAP, DP, 1 };
    gemm_dual<<<24, 256>>>(gx2, ge2, 16);

    final_k<<<NG, 256>>>(ws3, bs3, wmx3, wme3, (float*)d_out);
    (void)out_size;
}